// round 7
// baseline (speedup 1.0000x reference)
#include <cuda_runtime.h>
#include <cuda_fp16.h>
#include <cstddef>

#define MAX_N (512 * 512)
#define NB 8

// Cell table: for each grid cell c = jj*nx+ii, 4 x uint4 (one per batch-pair p).
// Each uint4 = 4 half2: (v00,v10,v01,v11), each half2 = (batch 2p, batch 2p+1).
// 64B per cell.
__device__ uint4 g_cell[(size_t)MAX_N * 4];

// Uniform constants computed once by prep: x0,y0,inv_dx,inv_dy,nxm2,nym2,nx(bits),0
__device__ __align__(16) float g_consts[8];

static __device__ __forceinline__ unsigned h2u(__half2 h) {
    return *reinterpret_cast<unsigned*>(&h);
}
static __device__ __forceinline__ __half2 u2h(unsigned u) {
    return *reinterpret_cast<__half2*>(&u);
}

// ---------------------------------------------------------------------------
// Prep v2: thread = (cell-quad q, batch-pair p), idx = q*4+p.
// Vector path (nx%4==0): 4x float4 row loads + 4 scalar tails per 4 cells.
// Also: thread 0 computes the uniform constants for the interp kernel.
// ---------------------------------------------------------------------------
__global__ void __launch_bounds__(256) prep_cell_v2(
    const float* __restrict__ x,
    const float* __restrict__ src_x,
    const float* __restrict__ src_y,
    const int* __restrict__ p_nx,
    const int* __restrict__ p_ny,
    int N)
{
    const int idx = blockIdx.x * blockDim.x + threadIdx.x;
    const int nx = p_nx[0];
    const int ny = p_ny[0];

    if (idx == 0) {
        const float x0 = src_x[0];
        const float x1 = src_x[nx - 1];
        const float y0 = src_y[0];
        const float y1 = src_y[(size_t)(ny - 1) * nx];
        g_consts[0] = x0;
        g_consts[1] = y0;
        g_consts[2] = (float)(nx - 1) / (x1 - x0);
        g_consts[3] = (float)(ny - 1) / (y1 - y0);
        g_consts[4] = (float)(nx - 2);
        g_consts[5] = (float)(ny - 2);
        g_consts[6] = __int_as_float(nx);
        g_consts[7] = 0.0f;
    }

    const int q = idx >> 2;          // cell quad
    const int p = idx & 3;           // batch pair
    const int c0 = q * 4;
    if (c0 >= N) return;

    const int jj  = c0 / nx;
    const int ii0 = c0 - jj * nx;
    if (jj > ny - 2) return;

    const float* __restrict__ xb0 = x + (size_t)(2 * p) * N;
    const float* __restrict__ xb1 = xb0 + N;

    if ((nx & 3) == 0) {
        // Quad never crosses a row (c0%4==0, nx%4==0).
        float r0[5], r1[5], s0[5], s1[5];
        float4 v;
        v = *reinterpret_cast<const float4*>(xb0 + c0);
        r0[0] = v.x; r0[1] = v.y; r0[2] = v.z; r0[3] = v.w;
        r0[4] = __ldg(xb0 + min(c0 + 4, N - 1));
        v = *reinterpret_cast<const float4*>(xb0 + c0 + nx);
        r1[0] = v.x; r1[1] = v.y; r1[2] = v.z; r1[3] = v.w;
        r1[4] = __ldg(xb0 + min(c0 + nx + 4, N - 1));
        v = *reinterpret_cast<const float4*>(xb1 + c0);
        s0[0] = v.x; s0[1] = v.y; s0[2] = v.z; s0[3] = v.w;
        s0[4] = __ldg(xb1 + min(c0 + 4, N - 1));
        v = *reinterpret_cast<const float4*>(xb1 + c0 + nx);
        s1[0] = v.x; s1[1] = v.y; s1[2] = v.z; s1[3] = v.w;
        s1[4] = __ldg(xb1 + min(c0 + nx + 4, N - 1));

#pragma unroll
        for (int i = 0; i < 4; i++) {
            if (ii0 + i <= nx - 2) {
                uint4 w;
                w.x = h2u(__floats2half2_rn(r0[i],     s0[i]));
                w.y = h2u(__floats2half2_rn(r0[i + 1], s0[i + 1]));
                w.z = h2u(__floats2half2_rn(r1[i],     s1[i]));
                w.w = h2u(__floats2half2_rn(r1[i + 1], s1[i + 1]));
                g_cell[(size_t)(c0 + i) * 4 + p] = w;
            }
        }
    } else {
        // Scalar fallback for odd nx.
#pragma unroll
        for (int i = 0; i < 4; i++) {
            const int c = c0 + i;
            if (c >= N) break;
            const int jr = c / nx;
            const int ir = c - jr * nx;
            if (ir > nx - 2 || jr > ny - 2) continue;
            uint4 w;
            w.x = h2u(__floats2half2_rn(__ldg(xb0 + c),          __ldg(xb1 + c)));
            w.y = h2u(__floats2half2_rn(__ldg(xb0 + c + 1),      __ldg(xb1 + c + 1)));
            w.z = h2u(__floats2half2_rn(__ldg(xb0 + c + nx),     __ldg(xb1 + c + nx)));
            w.w = h2u(__floats2half2_rn(__ldg(xb0 + c + nx + 1), __ldg(xb1 + c + nx + 1)));
            g_cell[(size_t)c * 4 + p] = w;
        }
    }
}

// ---------------------------------------------------------------------------
// Interp: lane (g,p): g=lane>>2 target group, p=lane&3 batch pair.
// Per target: one LDG.128 per lane (4 lanes = one 64B cell).
// Third vertex selected with a single u32 SEL on the packed half2;
// wA = |1 - (u+v)| encodes both triangle halves.
// ---------------------------------------------------------------------------
__global__ void __launch_bounds__(256) interp_fp16_v2(
    const float* __restrict__ tgt_x,
    const float* __restrict__ tgt_y,
    float* __restrict__ out,
    int T)
{
    const int lane = threadIdx.x & 31;
    const int warp = (blockIdx.x * blockDim.x + threadIdx.x) >> 5;
    const int g    = lane >> 2;
    const int p    = lane & 3;
    const int tg   = warp * 32 + g * 4;
    if (tg >= T) return;

    const float4 k0 = *reinterpret_cast<const float4*>(&g_consts[0]);
    const float4 k1 = *reinterpret_cast<const float4*>(&g_consts[4]);
    const float x0 = k0.x, y0 = k0.y, inv_dx = k0.z, inv_dy = k0.w;
    const float nxm2 = k1.x, nym2 = k1.y;
    const int nx = __float_as_int(k1.z);

    const bool full = (tg + 3 < T);

    float tx[4], ty[4];
    if (full) {
        const float4 tx4 = *reinterpret_cast<const float4*>(tgt_x + tg);
        const float4 ty4 = *reinterpret_cast<const float4*>(tgt_y + tg);
        tx[0] = tx4.x; tx[1] = tx4.y; tx[2] = tx4.z; tx[3] = tx4.w;
        ty[0] = ty4.x; ty[1] = ty4.y; ty[2] = ty4.z; ty[3] = ty4.w;
    } else {
#pragma unroll
        for (int j = 0; j < 4; j++) {
            const int t = min(tg + j, T - 1);
            tx[j] = tgt_x[t];
            ty[j] = tgt_y[t];
        }
    }

    float o0[4], o1[4];
#pragma unroll
    for (int j = 0; j < 4; j++) {
        const float fx = (tx[j] - x0) * inv_dx;
        const float fy = (ty[j] - y0) * inv_dy;
        const float ixf = fminf(fmaxf(floorf(fx), 0.0f), nxm2);
        const float iyf = fminf(fmaxf(floorf(fy), 0.0f), nym2);
        const float u = fx - ixf;
        const float v = fy - iyf;
        const int base = (int)iyf * nx + (int)ixf;

        const float s = u + v;
        const bool lower = (s <= 1.0f);
        const float wA  = fabsf(1.0f - s);
        const float w10 = lower ? u : (1.0f - v);
        const float w01 = lower ? v : (1.0f - u);

        const uint4 cv = __ldg(&g_cell[(size_t)base * 4 + p]);
        const unsigned ua = lower ? cv.x : cv.w;   // v00 or v11

        const float2 fA  = __half22float2(u2h(ua));
        const float2 f10 = __half22float2(u2h(cv.y));
        const float2 f01 = __half22float2(u2h(cv.z));

        o0[j] = wA * fA.x + w10 * f10.x + w01 * f01.x;
        o1[j] = wA * fA.y + w10 * f10.y + w01 * f01.y;
    }

    const int b0 = 2 * p;
    if (full) {
        *reinterpret_cast<float4*>(out + (size_t)b0 * T + tg) =
            make_float4(o0[0], o0[1], o0[2], o0[3]);
        *reinterpret_cast<float4*>(out + (size_t)(b0 + 1) * T + tg) =
            make_float4(o1[0], o1[1], o1[2], o1[3]);
    } else {
#pragma unroll
        for (int j = 0; j < 4; j++) {
            if (tg + j < T) {
                out[(size_t)b0 * T + tg + j] = o0[j];
                out[(size_t)(b0 + 1) * T + tg + j] = o1[j];
            }
        }
    }
}

// ---------------------------------------------------------------------------
// Generic fallback (any B), fp32 exact.
// ---------------------------------------------------------------------------
__global__ void interp_generic_kernel(
    const float* __restrict__ x,
    const float* __restrict__ src_x,
    const float* __restrict__ src_y,
    const float* __restrict__ tgt_x,
    const float* __restrict__ tgt_y,
    const int* __restrict__ p_nx,
    const int* __restrict__ p_ny,
    float* __restrict__ out,
    int T, int B, int N)
{
    int t = blockIdx.x * blockDim.x + threadIdx.x;
    if (t >= T) return;

    const int nx = p_nx[0];
    const int ny = p_ny[0];
    const float x0 = src_x[0];
    const float x1 = src_x[nx - 1];
    const float y0 = src_y[0];
    const float y1 = src_y[(size_t)(ny - 1) * nx];
    const float inv_dx = (float)(nx - 1) / (x1 - x0);
    const float inv_dy = (float)(ny - 1) / (y1 - y0);

    const float fx = (tgt_x[t] - x0) * inv_dx;
    const float fy = (tgt_y[t] - y0) * inv_dy;

    float ixf = fminf(fmaxf(floorf(fx), 0.0f), (float)(nx - 2));
    float iyf = fminf(fmaxf(floorf(fy), 0.0f), (float)(ny - 2));
    const float u = fx - ixf;
    const float v = fy - iyf;
    const int base = (int)iyf * nx + (int)ixf;

    const bool lower = (u + v <= 1.0f);
    const int iA = lower ? base : (base + nx + 1);
    const int iB = base + 1;
    const int iC = base + nx;
    const float wA = lower ? (1.0f - u - v) : (u + v - 1.0f);
    const float wB = lower ? u : (1.0f - v);
    const float wC = lower ? v : (1.0f - u);

    for (int b = 0; b < B; b++) {
        const float* xb = x + (size_t)b * N;
        out[(size_t)b * T + t] = wA * xb[iA] + wB * xb[iB] + wC * xb[iC];
    }
}

extern "C" void kernel_launch(void* const* d_in, const int* in_sizes, int n_in,
                              void* d_out, int out_size)
{
    const float* x     = (const float*)d_in[0];
    const float* src_x = (const float*)d_in[1];
    const float* src_y = (const float*)d_in[2];
    const float* tgt_x = (const float*)d_in[3];
    const float* tgt_y = (const float*)d_in[4];
    const int*   p_nx  = (const int*)d_in[5];
    const int*   p_ny  = (const int*)d_in[6];
    float* out = (float*)d_out;

    const int N = in_sizes[1];          // nx*ny grid points
    const int T = in_sizes[3];          // target count
    const int B = in_sizes[0] / N;      // batches

    if (B == NB && N <= MAX_N) {
        // prep: one thread per (cell-quad, pair) -> N threads total.
        const int prep_threads = ((N + 3) / 4) * 4;
        prep_cell_v2<<<(prep_threads + 255) / 256, 256>>>(
            x, src_x, src_y, p_nx, p_ny, N);
        const int blocks = (T + 255) / 256;
        interp_fp16_v2<<<blocks, 256>>>(tgt_x, tgt_y, out, T);
    } else {
        const int threads = 256;
        interp_generic_kernel<<<(T + threads - 1) / threads, threads>>>(
            x, src_x, src_y, tgt_x, tgt_y, p_nx, p_ny, out, T, B, N);
    }
}

// round 8
// speedup vs baseline: 1.0597x; 1.0597x over previous
#include <cuda_runtime.h>
#include <cuda_fp16.h>
#include <cstddef>

#define MAX_N (512 * 512)
#define NB 8

// Cell table: for each grid cell c = jj*nx+ii, 4 x uint4 (one per batch-pair p).
// Each uint4 = 4 half2: (v00,v10,v01,v11), each half2 = (batch 2p, batch 2p+1).
// 64B per cell.
__device__ uint4 g_cell[(size_t)MAX_N * 4];

// Uniform constants computed once by prep: x0,y0,inv_dx,inv_dy,nxm2,nym2,nx(bits),0
__device__ __align__(16) float g_consts[8];

static __device__ __forceinline__ unsigned h2u(__half2 h) {
    return *reinterpret_cast<unsigned*>(&h);
}
static __device__ __forceinline__ __half2 u2h(unsigned u) {
    return *reinterpret_cast<__half2*>(&u);
}

// ---------------------------------------------------------------------------
// Prep v2: thread = (cell-quad q, batch-pair p), idx = q*4+p.
// Vector path (nx%4==0): 4x float4 row loads + 4 scalar tails per 4 cells.
// Also: thread 0 computes the uniform constants for the interp kernel.
// ---------------------------------------------------------------------------
__global__ void __launch_bounds__(256) prep_cell_v2(
    const float* __restrict__ x,
    const float* __restrict__ src_x,
    const float* __restrict__ src_y,
    const int* __restrict__ p_nx,
    const int* __restrict__ p_ny,
    int N)
{
    const int idx = blockIdx.x * blockDim.x + threadIdx.x;
    const int nx = p_nx[0];
    const int ny = p_ny[0];

    if (idx == 0) {
        const float x0 = src_x[0];
        const float x1 = src_x[nx - 1];
        const float y0 = src_y[0];
        const float y1 = src_y[(size_t)(ny - 1) * nx];
        g_consts[0] = x0;
        g_consts[1] = y0;
        g_consts[2] = (float)(nx - 1) / (x1 - x0);
        g_consts[3] = (float)(ny - 1) / (y1 - y0);
        g_consts[4] = (float)(nx - 2);
        g_consts[5] = (float)(ny - 2);
        g_consts[6] = __int_as_float(nx);
        g_consts[7] = 0.0f;
    }

    const int q = idx >> 2;          // cell quad
    const int p = idx & 3;           // batch pair
    const int c0 = q * 4;
    if (c0 >= N) return;

    const int jj  = c0 / nx;
    const int ii0 = c0 - jj * nx;
    if (jj > ny - 2) return;

    const float* __restrict__ xb0 = x + (size_t)(2 * p) * N;
    const float* __restrict__ xb1 = xb0 + N;

    if ((nx & 3) == 0) {
        // Quad never crosses a row (c0%4==0, nx%4==0).
        float r0[5], r1[5], s0[5], s1[5];
        float4 v;
        v = *reinterpret_cast<const float4*>(xb0 + c0);
        r0[0] = v.x; r0[1] = v.y; r0[2] = v.z; r0[3] = v.w;
        r0[4] = __ldg(xb0 + min(c0 + 4, N - 1));
        v = *reinterpret_cast<const float4*>(xb0 + c0 + nx);
        r1[0] = v.x; r1[1] = v.y; r1[2] = v.z; r1[3] = v.w;
        r1[4] = __ldg(xb0 + min(c0 + nx + 4, N - 1));
        v = *reinterpret_cast<const float4*>(xb1 + c0);
        s0[0] = v.x; s0[1] = v.y; s0[2] = v.z; s0[3] = v.w;
        s0[4] = __ldg(xb1 + min(c0 + 4, N - 1));
        v = *reinterpret_cast<const float4*>(xb1 + c0 + nx);
        s1[0] = v.x; s1[1] = v.y; s1[2] = v.z; s1[3] = v.w;
        s1[4] = __ldg(xb1 + min(c0 + nx + 4, N - 1));

#pragma unroll
        for (int i = 0; i < 4; i++) {
            if (ii0 + i <= nx - 2) {
                uint4 w;
                w.x = h2u(__floats2half2_rn(r0[i],     s0[i]));
                w.y = h2u(__floats2half2_rn(r0[i + 1], s0[i + 1]));
                w.z = h2u(__floats2half2_rn(r1[i],     s1[i]));
                w.w = h2u(__floats2half2_rn(r1[i + 1], s1[i + 1]));
                g_cell[(size_t)(c0 + i) * 4 + p] = w;
            }
        }
    } else {
        // Scalar fallback for odd nx.
#pragma unroll
        for (int i = 0; i < 4; i++) {
            const int c = c0 + i;
            if (c >= N) break;
            const int jr = c / nx;
            const int ir = c - jr * nx;
            if (ir > nx - 2 || jr > ny - 2) continue;
            uint4 w;
            w.x = h2u(__floats2half2_rn(__ldg(xb0 + c),          __ldg(xb1 + c)));
            w.y = h2u(__floats2half2_rn(__ldg(xb0 + c + 1),      __ldg(xb1 + c + 1)));
            w.z = h2u(__floats2half2_rn(__ldg(xb0 + c + nx),     __ldg(xb1 + c + nx)));
            w.w = h2u(__floats2half2_rn(__ldg(xb0 + c + nx + 1), __ldg(xb1 + c + nx + 1)));
            g_cell[(size_t)c * 4 + p] = w;
        }
    }
}

// ---------------------------------------------------------------------------
// Interp: lane (g,p): g=lane>>2 target group, p=lane&3 batch pair.
// Per target: one LDG.128 per lane (4 lanes = one 64B cell).
// Third vertex selected with a single u32 SEL on the packed half2;
// wA = |1 - (u+v)| encodes both triangle halves.
// ---------------------------------------------------------------------------
__global__ void __launch_bounds__(256) interp_fp16_v2(
    const float* __restrict__ tgt_x,
    const float* __restrict__ tgt_y,
    float* __restrict__ out,
    int T)
{
    const int lane = threadIdx.x & 31;
    const int warp = (blockIdx.x * blockDim.x + threadIdx.x) >> 5;
    const int g    = lane >> 2;
    const int p    = lane & 3;
    const int tg   = warp * 32 + g * 4;
    if (tg >= T) return;

    const float4 k0 = *reinterpret_cast<const float4*>(&g_consts[0]);
    const float4 k1 = *reinterpret_cast<const float4*>(&g_consts[4]);
    const float x0 = k0.x, y0 = k0.y, inv_dx = k0.z, inv_dy = k0.w;
    const float nxm2 = k1.x, nym2 = k1.y;
    const int nx = __float_as_int(k1.z);

    const bool full = (tg + 3 < T);

    float tx[4], ty[4];
    if (full) {
        const float4 tx4 = *reinterpret_cast<const float4*>(tgt_x + tg);
        const float4 ty4 = *reinterpret_cast<const float4*>(tgt_y + tg);
        tx[0] = tx4.x; tx[1] = tx4.y; tx[2] = tx4.z; tx[3] = tx4.w;
        ty[0] = ty4.x; ty[1] = ty4.y; ty[2] = ty4.z; ty[3] = ty4.w;
    } else {
#pragma unroll
        for (int j = 0; j < 4; j++) {
            const int t = min(tg + j, T - 1);
            tx[j] = tgt_x[t];
            ty[j] = tgt_y[t];
        }
    }

    float o0[4], o1[4];
#pragma unroll
    for (int j = 0; j < 4; j++) {
        const float fx = (tx[j] - x0) * inv_dx;
        const float fy = (ty[j] - y0) * inv_dy;
        const float ixf = fminf(fmaxf(floorf(fx), 0.0f), nxm2);
        const float iyf = fminf(fmaxf(floorf(fy), 0.0f), nym2);
        const float u = fx - ixf;
        const float v = fy - iyf;
        const int base = (int)iyf * nx + (int)ixf;

        const float s = u + v;
        const bool lower = (s <= 1.0f);
        const float wA  = fabsf(1.0f - s);
        const float w10 = lower ? u : (1.0f - v);
        const float w01 = lower ? v : (1.0f - u);

        const uint4 cv = __ldg(&g_cell[(size_t)base * 4 + p]);
        const unsigned ua = lower ? cv.x : cv.w;   // v00 or v11

        const float2 fA  = __half22float2(u2h(ua));
        const float2 f10 = __half22float2(u2h(cv.y));
        const float2 f01 = __half22float2(u2h(cv.z));

        o0[j] = wA * fA.x + w10 * f10.x + w01 * f01.x;
        o1[j] = wA * fA.y + w10 * f10.y + w01 * f01.y;
    }

    const int b0 = 2 * p;
    if (full) {
        *reinterpret_cast<float4*>(out + (size_t)b0 * T + tg) =
            make_float4(o0[0], o0[1], o0[2], o0[3]);
        *reinterpret_cast<float4*>(out + (size_t)(b0 + 1) * T + tg) =
            make_float4(o1[0], o1[1], o1[2], o1[3]);
    } else {
#pragma unroll
        for (int j = 0; j < 4; j++) {
            if (tg + j < T) {
                out[(size_t)b0 * T + tg + j] = o0[j];
                out[(size_t)(b0 + 1) * T + tg + j] = o1[j];
            }
        }
    }
}

// ---------------------------------------------------------------------------
// Generic fallback (any B), fp32 exact.
// ---------------------------------------------------------------------------
__global__ void interp_generic_kernel(
    const float* __restrict__ x,
    const float* __restrict__ src_x,
    const float* __restrict__ src_y,
    const float* __restrict__ tgt_x,
    const float* __restrict__ tgt_y,
    const int* __restrict__ p_nx,
    const int* __restrict__ p_ny,
    float* __restrict__ out,
    int T, int B, int N)
{
    int t = blockIdx.x * blockDim.x + threadIdx.x;
    if (t >= T) return;

    const int nx = p_nx[0];
    const int ny = p_ny[0];
    const float x0 = src_x[0];
    const float x1 = src_x[nx - 1];
    const float y0 = src_y[0];
    const float y1 = src_y[(size_t)(ny - 1) * nx];
    const float inv_dx = (float)(nx - 1) / (x1 - x0);
    const float inv_dy = (float)(ny - 1) / (y1 - y0);

    const float fx = (tgt_x[t] - x0) * inv_dx;
    const float fy = (tgt_y[t] - y0) * inv_dy;

    float ixf = fminf(fmaxf(floorf(fx), 0.0f), (float)(nx - 2));
    float iyf = fminf(fmaxf(floorf(fy), 0.0f), (float)(ny - 2));
    const float u = fx - ixf;
    const float v = fy - iyf;
    const int base = (int)iyf * nx + (int)ixf;

    const bool lower = (u + v <= 1.0f);
    const int iA = lower ? base : (base + nx + 1);
    const int iB = base + 1;
    const int iC = base + nx;
    const float wA = lower ? (1.0f - u - v) : (u + v - 1.0f);
    const float wB = lower ? u : (1.0f - v);
    const float wC = lower ? v : (1.0f - u);

    for (int b = 0; b < B; b++) {
        const float* xb = x + (size_t)b * N;
        out[(size_t)b * T + t] = wA * xb[iA] + wB * xb[iB] + wC * xb[iC];
    }
}

extern "C" void kernel_launch(void* const* d_in, const int* in_sizes, int n_in,
                              void* d_out, int out_size)
{
    const float* x     = (const float*)d_in[0];
    const float* src_x = (const float*)d_in[1];
    const float* src_y = (const float*)d_in[2];
    const float* tgt_x = (const float*)d_in[3];
    const float* tgt_y = (const float*)d_in[4];
    const int*   p_nx  = (const int*)d_in[5];
    const int*   p_ny  = (const int*)d_in[6];
    float* out = (float*)d_out;

    const int N = in_sizes[1];          // nx*ny grid points
    const int T = in_sizes[3];          // target count
    const int B = in_sizes[0] / N;      // batches

    if (B == NB && N <= MAX_N) {
        // prep: one thread per (cell-quad, pair) -> N threads total.
        const int prep_threads = ((N + 3) / 4) * 4;
        prep_cell_v2<<<(prep_threads + 255) / 256, 256>>>(
            x, src_x, src_y, p_nx, p_ny, N);
        const int blocks = (T + 255) / 256;
        interp_fp16_v2<<<blocks, 256>>>(tgt_x, tgt_y, out, T);
    } else {
        const int threads = 256;
        interp_generic_kernel<<<(T + threads - 1) / threads, threads>>>(
            x, src_x, src_y, tgt_x, tgt_y, p_nx, p_ny, out, T, B, N);
    }
}